// round 1
// baseline (speedup 1.0000x reference)
#include <cuda_runtime.h>

#define B__   256
#define NTOK  196
#define CDIM  256
#define NH    8
#define HDIM  32
#define NWIN  64
#define MROWS (B__ * NTOK)          // 50176
#define QSCALE 0.17677669529663687f // 1/sqrt(32)

// Scratch (device globals — no allocation allowed)
__device__ float g_q[MROWS * CDIM]; // [B][H][N][hd], pre-scaled
__device__ float g_k[MROWS * CDIM]; // [B][H][N][hd]
__device__ float g_v[MROWS * CDIM]; // [B][H][N][hd]
__device__ float g_o[MROWS * CDIM]; // [B][N][C] attention output

// ---------------------------------------------------------------------------
// Tiled fp32 GEMM:  Y[r][c] = sum_k A[r][k] * W[c][k] + bias[c]
// MODE 0: A = x (param), scatter into g_q/g_k/g_v with q-scaling
// MODE 1: A = g_o,       store to out (final proj)
// Tile 64x64, BK=16, 256 threads, 4x4 per thread, float4 IO.
// ---------------------------------------------------------------------------
template <int MODE>
__global__ __launch_bounds__(256) void gemm_kernel(
    const float* __restrict__ Ain, const float* __restrict__ W,
    const float* __restrict__ bias, float* __restrict__ out)
{
    const int K = 256;
    const float* A = (MODE == 0) ? Ain : g_o;

    __shared__ float As[16][64];
    __shared__ float Bs[16][64];

    const int lin = threadIdx.x;
    const int rowBase = blockIdx.y * 64;
    const int colBase = blockIdx.x * 64;
    const int lrow = lin >> 2;
    const int lks  = (lin & 3) << 2;
    const int tx = lin & 15, ty = lin >> 4;

    float acc[4][4] = {};

    for (int kt = 0; kt < K; kt += 16) {
        float4 av = *(const float4*)&A[(size_t)(rowBase + lrow) * K + kt + lks];
        float4 bv = *(const float4*)&W[(size_t)(colBase + lrow) * K + kt + lks];
        As[lks + 0][lrow] = av.x; As[lks + 1][lrow] = av.y;
        As[lks + 2][lrow] = av.z; As[lks + 3][lrow] = av.w;
        Bs[lks + 0][lrow] = bv.x; Bs[lks + 1][lrow] = bv.y;
        Bs[lks + 2][lrow] = bv.z; Bs[lks + 3][lrow] = bv.w;
        __syncthreads();
#pragma unroll
        for (int kk = 0; kk < 16; kk++) {
            float4 a = *(const float4*)&As[kk][ty << 2];
            float4 b = *(const float4*)&Bs[kk][tx << 2];
            float af[4] = {a.x, a.y, a.z, a.w};
            float bf[4] = {b.x, b.y, b.z, b.w};
#pragma unroll
            for (int i = 0; i < 4; i++)
#pragma unroll
                for (int j = 0; j < 4; j++) acc[i][j] += af[i] * bf[j];
        }
        __syncthreads();
    }

    const int c0 = colBase + (tx << 2);
    float4 b4;
    b4.x = bias[c0 + 0]; b4.y = bias[c0 + 1];
    b4.z = bias[c0 + 2]; b4.w = bias[c0 + 3];

#pragma unroll
    for (int i = 0; i < 4; i++) {
        const int r = rowBase + (ty << 2) + i;
        float4 v;
        v.x = acc[i][0] + b4.x; v.y = acc[i][1] + b4.y;
        v.z = acc[i][2] + b4.z; v.w = acc[i][3] + b4.w;
        if (MODE == 0) {
            const int bb = r / NTOK, nn = r - bb * NTOK;
            const int s = c0 >> 8, hh = (c0 >> 5) & 7, dd = c0 & 31;
            float* dst = (s == 0) ? g_q : (s == 1) ? g_k : g_v;
            if (s == 0) { v.x *= QSCALE; v.y *= QSCALE; v.z *= QSCALE; v.w *= QSCALE; }
            *(float4*)&dst[(size_t)(((bb * NH + hh) * NTOK + nn) * HDIM + dd)] = v;
        } else {
            *(float4*)&out[(size_t)r * CDIM + c0] = v;
        }
    }
}

// ---------------------------------------------------------------------------
// Fused attention: one CTA per (b, h). K^T and V resident in SMEM.
// 8 warps, each warp owns one q-row at a time (row = warp, warp+8, ...).
// Lane l owns score columns m in {4l..4l+3} and {128+4l..131+4l | l<17}.
// SMEM (floats): Kt[32][200] | Vs[196*32] | biasCol[1183+1] | Pb[8][200] | Qs[8][32]
// ---------------------------------------------------------------------------
#define SM_KT 0
#define SM_VS 6400
#define SM_BC 12672
#define SM_PB 13856
#define SM_QS 15456
#define SM_FLOATS 15712
#define ATTN_SMEM_BYTES (SM_FLOATS * 4)

__global__ __launch_bounds__(256) void attn_kernel(
    const float* __restrict__ mask, const float* __restrict__ bias_table,
    const int* __restrict__ rel_index)
{
    extern __shared__ float sm[];
    float* Kt = sm + SM_KT;
    float* Vs = sm + SM_VS;
    float* Bc = sm + SM_BC;
    float* Qs = sm + SM_QS;

    const int tid = threadIdx.x;
    const int lane = tid & 31, warp = tid >> 5;
    const int bh = blockIdx.x;
    const int b = bh >> 3, h = bh & 7;
    const size_t base = (size_t)bh * (NTOK * HDIM);

    // Fill K^T (padded stride 200), V, bias column for this head
    for (int idx = tid; idx < NTOK * HDIM; idx += 256) {
        const int m = idx >> 5, d = idx & 31;
        Kt[d * 200 + m] = g_k[base + idx];
        Vs[idx] = g_v[base + idx];
    }
    for (int i = tid; i < 1183; i += 256) Bc[i] = bias_table[i * NH + h];
    __syncthreads();

    const float4* Kt4 = (const float4*)Kt;              // stride 50 per d
    float4* Pb4 = (float4*)(sm + SM_PB) + warp * 50;    // per-warp P row
    const int* riB = rel_index;
    const float* mkB = mask + (size_t)(b & 63) * (NTOK * NTOK);
    const bool g2 = (lane < 17);

    for (int row = warp; row < NTOK; row += 8) {
        Qs[warp * 32 + lane] = g_q[base + row * HDIM + lane];
        __syncwarp();

        float S[8] = {0.f, 0.f, 0.f, 0.f, 0.f, 0.f, 0.f, 0.f};
#pragma unroll
        for (int d = 0; d < 32; d++) {
            const float qd = Qs[warp * 32 + d];
            const float4 k0 = Kt4[d * 50 + lane];
            S[0] += qd * k0.x; S[1] += qd * k0.y;
            S[2] += qd * k0.z; S[3] += qd * k0.w;
            if (g2) {
                const float4 k1 = Kt4[d * 50 + 32 + lane];
                S[4] += qd * k1.x; S[5] += qd * k1.y;
                S[6] += qd * k1.z; S[7] += qd * k1.w;
            }
        }

        // relative-position bias + window mask
        {
            const int4   r0 = ((const int4*)(riB + row * NTOK))[lane];
            const float4 m0 = ((const float4*)(mkB + row * NTOK))[lane];
            S[0] += Bc[r0.x] + m0.x; S[1] += Bc[r0.y] + m0.y;
            S[2] += Bc[r0.z] + m0.z; S[3] += Bc[r0.w] + m0.w;
            if (g2) {
                const int4   r1 = ((const int4*)(riB + row * NTOK))[32 + lane];
                const float4 m1 = ((const float4*)(mkB + row * NTOK))[32 + lane];
                S[4] += Bc[r1.x] + m1.x; S[5] += Bc[r1.y] + m1.y;
                S[6] += Bc[r1.z] + m1.z; S[7] += Bc[r1.w] + m1.w;
            }
        }

        // softmax over the 196 columns
        float mx = fmaxf(fmaxf(S[0], S[1]), fmaxf(S[2], S[3]));
        if (g2) mx = fmaxf(mx, fmaxf(fmaxf(S[4], S[5]), fmaxf(S[6], S[7])));
#pragma unroll
        for (int off = 16; off; off >>= 1)
            mx = fmaxf(mx, __shfl_xor_sync(0xffffffffu, mx, off));

        float sum = 0.f;
#pragma unroll
        for (int j = 0; j < 4; j++) { S[j] = __expf(S[j] - mx); sum += S[j]; }
        if (g2) {
#pragma unroll
            for (int j = 4; j < 8; j++) { S[j] = __expf(S[j] - mx); sum += S[j]; }
        }
#pragma unroll
        for (int off = 16; off; off >>= 1)
            sum += __shfl_xor_sync(0xffffffffu, sum, off);
        const float inv = 1.0f / sum;
#pragma unroll
        for (int j = 0; j < 8; j++) S[j] *= inv;

        // stage P to SMEM (float4 per group)
        Pb4[lane] = make_float4(S[0], S[1], S[2], S[3]);
        if (g2) Pb4[32 + lane] = make_float4(S[4], S[5], S[6], S[7]);
        __syncwarp();

        // out[d=lane] = sum_m P[m] * V[m][d]
        float acc = 0.f;
        const float4* Pr = (const float4*)Pb4;
#pragma unroll 7
        for (int g = 0; g < 49; g++) {
            const float4 p = Pr[g];
            const float* vr = Vs + g * 128 + lane;
            acc += p.x * vr[0];
            acc += p.y * vr[32];
            acc += p.z * vr[64];
            acc += p.w * vr[96];
        }
        g_o[((size_t)b * NTOK + row) * CDIM + h * HDIM + lane] = acc;
        __syncwarp();
    }
}

// ---------------------------------------------------------------------------
extern "C" void kernel_launch(void* const* d_in, const int* in_sizes, int n_in,
                              void* d_out, int out_size)
{
    const float* x          = (const float*)d_in[0];
    const float* mask       = (const float*)d_in[1];
    const float* qkv_w      = (const float*)d_in[2];
    const float* qkv_b      = (const float*)d_in[3];
    const float* proj_w     = (const float*)d_in[4];
    const float* proj_b     = (const float*)d_in[5];
    const float* bias_table = (const float*)d_in[6];
    const int*   rel_index  = (const int*)d_in[7];
    float* out = (float*)d_out;

    cudaFuncSetAttribute(attn_kernel,
                         cudaFuncAttributeMaxDynamicSharedMemorySize,
                         ATTN_SMEM_BYTES);

    // 1) QKV projection -> g_q (scaled), g_k, g_v
    gemm_kernel<0><<<dim3(12, MROWS / 64), 256>>>(x, qkv_w, qkv_b, nullptr);
    // 2) fused window attention -> g_o [B][N][C]
    attn_kernel<<<B__ * NH, 256, ATTN_SMEM_BYTES>>>(mask, bias_table, rel_index);
    // 3) output projection -> d_out
    gemm_kernel<1><<<dim3(4, MROWS / 64), 256>>>(nullptr, proj_w, proj_b, out);
}

// round 2
// speedup vs baseline: 1.6000x; 1.6000x over previous
#include <cuda_runtime.h>

#define B__   256
#define NTOK  196
#define CDIM  256
#define NH    8
#define HDIM  32
#define MROWS (B__ * NTOK)          // 50176
#define QSCALE 0.17677669529663687f // 1/sqrt(32)

// Scratch (device globals — no allocation allowed)
__device__ float g_q[MROWS * CDIM]; // [B][H][N][hd], pre-scaled
__device__ float g_k[MROWS * CDIM]; // [B][H][N][hd]
__device__ float g_v[MROWS * CDIM]; // [B][H][N][hd]
__device__ float g_o[MROWS * CDIM]; // [B][N][C] attention output

// ---------------------------------------------------------------------------
// Tiled fp32 GEMM:  Y[r][c] = sum_k A[r][k] * W[c][k] + bias[c]
// MODE 0: A = x (param), scatter into g_q/g_k/g_v with q-scaling
// MODE 1: A = g_o,       store to out (final proj)
// Tile 128x128, BK=8, 256 threads, 8x8 per thread, double-buffered smem.
// ---------------------------------------------------------------------------
template <int MODE>
__global__ __launch_bounds__(256) void gemm_kernel(
    const float* __restrict__ Ain, const float* __restrict__ W,
    const float* __restrict__ bias, float* __restrict__ out)
{
    const float* A = (MODE == 0) ? Ain : g_o;

    __shared__ float As[2][8][128];
    __shared__ float Bs[2][8][128];

    const int tid = threadIdx.x;
    const int tx = tid & 15, ty = tid >> 4;
    const int rowBase = blockIdx.y << 7;
    const int colBase = blockIdx.x << 7;
    const int lr = tid >> 1;          // 0..127 tile row (for loading)
    const int lk = (tid & 1) << 2;    // 0 or 4

    const float* Arow = A + (size_t)(rowBase + lr) * 256 + lk;
    const float* Wrow = W + (size_t)(colBase + lr) * 256 + lk;

    // preload k-tile 0
    {
        float4 av = *(const float4*)Arow;
        float4 bv = *(const float4*)Wrow;
        As[0][lk + 0][lr] = av.x; As[0][lk + 1][lr] = av.y;
        As[0][lk + 2][lr] = av.z; As[0][lk + 3][lr] = av.w;
        Bs[0][lk + 0][lr] = bv.x; Bs[0][lk + 1][lr] = bv.y;
        Bs[0][lk + 2][lr] = bv.z; Bs[0][lk + 3][lr] = bv.w;
    }
    __syncthreads();

    float acc[8][8] = {};
    int buf = 0;

    for (int kt = 0; kt < 256; kt += 8) {
        float4 avn, bvn;
        const bool hn = (kt + 8) < 256;
        if (hn) {
            avn = *(const float4*)(Arow + kt + 8);
            bvn = *(const float4*)(Wrow + kt + 8);
        }
#pragma unroll
        for (int kk = 0; kk < 8; kk++) {
            const float4 a0 = *(const float4*)&As[buf][kk][ty << 2];
            const float4 a1 = *(const float4*)&As[buf][kk][(ty << 2) + 64];
            const float4 b0 = *(const float4*)&Bs[buf][kk][tx << 2];
            const float4 b1 = *(const float4*)&Bs[buf][kk][(tx << 2) + 64];
            const float ar[8] = {a0.x, a0.y, a0.z, a0.w, a1.x, a1.y, a1.z, a1.w};
            const float br[8] = {b0.x, b0.y, b0.z, b0.w, b1.x, b1.y, b1.z, b1.w};
#pragma unroll
            for (int i = 0; i < 8; i++)
#pragma unroll
                for (int j = 0; j < 8; j++) acc[i][j] += ar[i] * br[j];
        }
        if (hn) {
            const int nb = buf ^ 1;
            As[nb][lk + 0][lr] = avn.x; As[nb][lk + 1][lr] = avn.y;
            As[nb][lk + 2][lr] = avn.z; As[nb][lk + 3][lr] = avn.w;
            Bs[nb][lk + 0][lr] = bvn.x; Bs[nb][lk + 1][lr] = bvn.y;
            Bs[nb][lk + 2][lr] = bvn.z; Bs[nb][lk + 3][lr] = bvn.w;
            __syncthreads();
            buf = nb;
        }
    }

    // epilogue: rows = rowBase + ty*4 + io*64 + i ; cols = colBase + tx*4 + jo*64 + j
    float bfrag[2][4];
#pragma unroll
    for (int jo = 0; jo < 2; jo++) {
        const int c0 = colBase + (tx << 2) + jo * 64;
        bfrag[jo][0] = bias[c0 + 0]; bfrag[jo][1] = bias[c0 + 1];
        bfrag[jo][2] = bias[c0 + 2]; bfrag[jo][3] = bias[c0 + 3];
    }
#pragma unroll
    for (int io = 0; io < 2; io++) {
#pragma unroll
        for (int i = 0; i < 4; i++) {
            const int r = rowBase + (ty << 2) + io * 64 + i;
#pragma unroll
            for (int jo = 0; jo < 2; jo++) {
                const int c0 = colBase + (tx << 2) + jo * 64;
                float4 v;
                v.x = acc[io * 4 + i][jo * 4 + 0] + bfrag[jo][0];
                v.y = acc[io * 4 + i][jo * 4 + 1] + bfrag[jo][1];
                v.z = acc[io * 4 + i][jo * 4 + 2] + bfrag[jo][2];
                v.w = acc[io * 4 + i][jo * 4 + 3] + bfrag[jo][3];
                if (MODE == 0) {
                    const int bb = r / NTOK, nn = r - bb * NTOK;
                    const int s = c0 >> 8, hh = (c0 >> 5) & 7, dd = c0 & 31;
                    float* dst = (s == 0) ? g_q : (s == 1) ? g_k : g_v;
                    if (s == 0) { v.x *= QSCALE; v.y *= QSCALE; v.z *= QSCALE; v.w *= QSCALE; }
                    *(float4*)&dst[(size_t)(((bb * NH + hh) * NTOK + nn) * HDIM + dd)] = v;
                } else {
                    *(float4*)&out[(size_t)r * CDIM + c0] = v;
                }
            }
        }
    }
}

// ---------------------------------------------------------------------------
// Fused attention: one CTA per (b, h). K^T and V resident in SMEM.
// 8 warps, each warp processes 4 q-rows at a time (K/V fragments amortized).
// Lane l owns score columns m in {4l..4l+3} and {128+4l..131+4l | l<17}.
// SMEM (floats): Kt[32][200] | Vs[196*32] | Bc[1184] | Pb[8][4][200] | Qs[8][4][32]
// ---------------------------------------------------------------------------
#define SM_KT 0
#define SM_VS 6400
#define SM_BC 12672
#define SM_PB 13856
#define SM_QS 20256
#define SM_FLOATS 21280
#define ATTN_SMEM_BYTES (SM_FLOATS * 4)

__global__ __launch_bounds__(256) void attn_kernel(
    const float* __restrict__ mask, const float* __restrict__ bias_table,
    const int* __restrict__ rel_index)
{
    extern __shared__ float sm[];
    float* Kt = sm + SM_KT;
    float* Vs = sm + SM_VS;
    float* Bc = sm + SM_BC;

    const int tid = threadIdx.x;
    const int lane = tid & 31, warp = tid >> 5;
    const int bh = blockIdx.x;
    const int b = bh >> 3, h = bh & 7;
    const size_t base = (size_t)bh * (NTOK * HDIM);

    // Fill K^T (padded stride 200), V, bias column for this head
    for (int idx = tid; idx < NTOK * HDIM; idx += 256) {
        const int m = idx >> 5, d = idx & 31;
        Kt[d * 200 + m] = g_k[base + idx];
        Vs[idx] = g_v[base + idx];
    }
    for (int i = tid; i < 1183; i += 256) Bc[i] = bias_table[i * NH + h];
    __syncthreads();

    const float4* Kt4 = (const float4*)Kt;              // stride 50 per d
    const int* riB = rel_index;
    const float* mkB = mask + (size_t)(b & 63) * (NTOK * NTOK);
    const bool g2 = (lane < 17);
    float* Qw = sm + SM_QS + warp * 128;                // [4][32]
    float* Pw = sm + SM_PB + warp * 800;                // [4][200]

    for (int row0 = warp * 4; row0 < NTOK; row0 += 32) {
        // stage 4 q rows
#pragma unroll
        for (int r = 0; r < 4; r++)
            Qw[r * 32 + lane] = g_q[base + (size_t)(row0 + r) * HDIM + lane];
        __syncwarp();

        float S[4][8];
#pragma unroll
        for (int r = 0; r < 4; r++)
#pragma unroll
            for (int j = 0; j < 8; j++) S[r][j] = 0.f;

        // QK^T: 4 rows share each K fragment
#pragma unroll 8
        for (int d = 0; d < 32; d++) {
            const float4 k0 = Kt4[d * 50 + lane];
            float4 k1;
            if (g2) k1 = Kt4[d * 50 + 32 + lane];
#pragma unroll
            for (int r = 0; r < 4; r++) {
                const float q = Qw[r * 32 + d];
                S[r][0] += q * k0.x; S[r][1] += q * k0.y;
                S[r][2] += q * k0.z; S[r][3] += q * k0.w;
                if (g2) {
                    S[r][4] += q * k1.x; S[r][5] += q * k1.y;
                    S[r][6] += q * k1.z; S[r][7] += q * k1.w;
                }
            }
        }

        // bias + mask + softmax + stage P, per row
#pragma unroll
        for (int r = 0; r < 4; r++) {
            const int row = row0 + r;
            {
                const int4   i0 = ((const int4*)(riB + row * NTOK))[lane];
                const float4 m0 = ((const float4*)(mkB + (size_t)row * NTOK))[lane];
                S[r][0] += Bc[i0.x] + m0.x; S[r][1] += Bc[i0.y] + m0.y;
                S[r][2] += Bc[i0.z] + m0.z; S[r][3] += Bc[i0.w] + m0.w;
                if (g2) {
                    const int4   i1 = ((const int4*)(riB + row * NTOK))[32 + lane];
                    const float4 m1 = ((const float4*)(mkB + (size_t)row * NTOK))[32 + lane];
                    S[r][4] += Bc[i1.x] + m1.x; S[r][5] += Bc[i1.y] + m1.y;
                    S[r][6] += Bc[i1.z] + m1.z; S[r][7] += Bc[i1.w] + m1.w;
                }
            }
            float mx = fmaxf(fmaxf(S[r][0], S[r][1]), fmaxf(S[r][2], S[r][3]));
            if (g2) mx = fmaxf(mx, fmaxf(fmaxf(S[r][4], S[r][5]), fmaxf(S[r][6], S[r][7])));
#pragma unroll
            for (int off = 16; off; off >>= 1)
                mx = fmaxf(mx, __shfl_xor_sync(0xffffffffu, mx, off));

            float sum = 0.f;
#pragma unroll
            for (int j = 0; j < 4; j++) { S[r][j] = __expf(S[r][j] - mx); sum += S[r][j]; }
            if (g2) {
#pragma unroll
                for (int j = 4; j < 8; j++) { S[r][j] = __expf(S[r][j] - mx); sum += S[r][j]; }
            }
#pragma unroll
            for (int off = 16; off; off >>= 1)
                sum += __shfl_xor_sync(0xffffffffu, sum, off);
            const float inv = 1.0f / sum;
#pragma unroll
            for (int j = 0; j < 8; j++) S[r][j] *= inv;

            ((float4*)(Pw + r * 200))[lane] = make_float4(S[r][0], S[r][1], S[r][2], S[r][3]);
            if (g2)
                ((float4*)(Pw + r * 200))[32 + lane] = make_float4(S[r][4], S[r][5], S[r][6], S[r][7]);
        }
        __syncwarp();

        // PV: out[d=lane] per row; V fragment amortized over 4 rows
        float acc[4] = {0.f, 0.f, 0.f, 0.f};
#pragma unroll 7
        for (int g = 0; g < 49; g++) {
            const float* vr = Vs + g * 128 + lane;
            const float v0 = vr[0], v1 = vr[32], v2 = vr[64], v3 = vr[96];
#pragma unroll
            for (int r = 0; r < 4; r++) {
                const float4 p = ((const float4*)(Pw + r * 200))[g];
                acc[r] += p.x * v0 + p.y * v1 + p.z * v2 + p.w * v3;
            }
        }
#pragma unroll
        for (int r = 0; r < 4; r++)
            g_o[((size_t)b * NTOK + row0 + r) * CDIM + h * HDIM + lane] = acc[r];
        __syncwarp();
    }
}

// ---------------------------------------------------------------------------
extern "C" void kernel_launch(void* const* d_in, const int* in_sizes, int n_in,
                              void* d_out, int out_size)
{
    const float* x          = (const float*)d_in[0];
    const float* mask       = (const float*)d_in[1];
    const float* qkv_w      = (const float*)d_in[2];
    const float* qkv_b      = (const float*)d_in[3];
    const float* proj_w     = (const float*)d_in[4];
    const float* proj_b     = (const float*)d_in[5];
    const float* bias_table = (const float*)d_in[6];
    const int*   rel_index  = (const int*)d_in[7];
    float* out = (float*)d_out;

    cudaFuncSetAttribute(attn_kernel,
                         cudaFuncAttributeMaxDynamicSharedMemorySize,
                         ATTN_SMEM_BYTES);

    // 1) QKV projection -> g_q (scaled), g_k, g_v   (M=50176, N=768, K=256)
    gemm_kernel<0><<<dim3(6, MROWS / 128), 256>>>(x, qkv_w, qkv_b, nullptr);
    // 2) fused window attention -> g_o [B][N][C]
    attn_kernel<<<B__ * NH, 256, ATTN_SMEM_BYTES>>>(mask, bias_table, rel_index);
    // 3) output projection -> d_out                 (M=50176, N=256, K=256)
    gemm_kernel<1><<<dim3(2, MROWS / 128), 256>>>(nullptr, proj_w, proj_b, out);
}

// round 3
// speedup vs baseline: 1.6061x; 1.0038x over previous
#include <cuda_runtime.h>

#define B__   256
#define NTOK  196
#define CDIM  256
#define NH    8
#define HDIM  32
#define MROWS (B__ * NTOK)          // 50176
#define QSCALE 0.17677669529663687f // 1/sqrt(32)

typedef unsigned long long ull;

// packed fp32x2 helpers (Blackwell FFMA2 — only reachable via PTX)
#define FMA2(d, a, b, c) \
    asm("fma.rn.f32x2 %0, %1, %2, %3;" : "=l"(d) : "l"(a), "l"(b), "l"(c))

__device__ __forceinline__ ull pack2(float lo, float hi) {
    ull r; asm("mov.b64 %0, {%1, %2};" : "=l"(r) : "f"(lo), "f"(hi)); return r;
}
__device__ __forceinline__ float2 unpack2(ull v) {
    float2 f; asm("mov.b64 {%0, %1}, %2;" : "=f"(f.x), "=f"(f.y) : "l"(v)); return f;
}

// Scratch (device globals — no allocation allowed)
__device__ float g_q[MROWS * CDIM]; // [B][H][N][hd], pre-scaled
__device__ float g_k[MROWS * CDIM]; // [B][H][N][hd]
__device__ float g_v[MROWS * CDIM]; // [B][H][N][hd]
__device__ float g_o[MROWS * CDIM]; // [B][N][C] attention output

// ---------------------------------------------------------------------------
// Tiled fp32 GEMM with packed FFMA2:  Y[r][c] = sum_k A[r][k]*W[c][k] + bias[c]
// MODE 0: A = x, scatter into g_q/g_k/g_v with q-scaling
// MODE 1: A = g_o, store to out (final proj)
// Tile 128x128, BK=8, 256 threads, 8x8 per thread (as 8x4 f32x2 pairs).
// ---------------------------------------------------------------------------
template <int MODE>
__global__ __launch_bounds__(256) void gemm_kernel(
    const float* __restrict__ Ain, const float* __restrict__ W,
    const float* __restrict__ bias, float* __restrict__ out)
{
    const float* A = (MODE == 0) ? Ain : g_o;

    __shared__ float As[2][8][128];
    __shared__ float Bs[2][8][128];

    const int tid = threadIdx.x;
    const int tx = tid & 15, ty = tid >> 4;
    const int rowBase = blockIdx.y << 7;
    const int colBase = blockIdx.x << 7;
    const int lr = tid >> 1;          // 0..127 tile row (for loading)
    const int lk = (tid & 1) << 2;    // 0 or 4

    const float* Arow = A + (size_t)(rowBase + lr) * 256 + lk;
    const float* Wrow = W + (size_t)(colBase + lr) * 256 + lk;

    // preload k-tile 0
    {
        float4 av = *(const float4*)Arow;
        float4 bv = *(const float4*)Wrow;
        As[0][lk + 0][lr] = av.x; As[0][lk + 1][lr] = av.y;
        As[0][lk + 2][lr] = av.z; As[0][lk + 3][lr] = av.w;
        Bs[0][lk + 0][lr] = bv.x; Bs[0][lk + 1][lr] = bv.y;
        Bs[0][lk + 2][lr] = bv.z; Bs[0][lk + 3][lr] = bv.w;
    }
    __syncthreads();

    ull acc2[8][4] = {};  // [i][jpair] — bit pattern 0 == (0.f, 0.f)
    int buf = 0;

    for (int kt = 0; kt < 256; kt += 8) {
        float4 avn, bvn;
        const bool hn = (kt + 8) < 256;
        if (hn) {
            avn = *(const float4*)(Arow + kt + 8);
            bvn = *(const float4*)(Wrow + kt + 8);
        }
#pragma unroll
        for (int kk = 0; kk < 8; kk++) {
            const float4 a0 = *(const float4*)&As[buf][kk][ty << 2];
            const float4 a1 = *(const float4*)&As[buf][kk][(ty << 2) + 64];
            const float4 b0 = *(const float4*)&Bs[buf][kk][tx << 2];
            const float4 b1 = *(const float4*)&Bs[buf][kk][(tx << 2) + 64];
            const float af[8] = {a0.x, a0.y, a0.z, a0.w, a1.x, a1.y, a1.z, a1.w};
            ull ap[8];
#pragma unroll
            for (int i = 0; i < 8; i++) ap[i] = pack2(af[i], af[i]);
            const ull bp[4] = {pack2(b0.x, b0.y), pack2(b0.z, b0.w),
                               pack2(b1.x, b1.y), pack2(b1.z, b1.w)};
#pragma unroll
            for (int i = 0; i < 8; i++)
#pragma unroll
                for (int j = 0; j < 4; j++)
                    FMA2(acc2[i][j], ap[i], bp[j], acc2[i][j]);
        }
        if (hn) {
            const int nb = buf ^ 1;
            As[nb][lk + 0][lr] = avn.x; As[nb][lk + 1][lr] = avn.y;
            As[nb][lk + 2][lr] = avn.z; As[nb][lk + 3][lr] = avn.w;
            Bs[nb][lk + 0][lr] = bvn.x; Bs[nb][lk + 1][lr] = bvn.y;
            Bs[nb][lk + 2][lr] = bvn.z; Bs[nb][lk + 3][lr] = bvn.w;
            __syncthreads();
            buf = nb;
        }
    }

    // epilogue: rows = rowBase + ty*4 + io*64 + i ; cols = colBase + tx*4 + jo*64 + j
    float bfrag[2][4];
#pragma unroll
    for (int jo = 0; jo < 2; jo++) {
        const int c0 = colBase + (tx << 2) + jo * 64;
        bfrag[jo][0] = bias[c0 + 0]; bfrag[jo][1] = bias[c0 + 1];
        bfrag[jo][2] = bias[c0 + 2]; bfrag[jo][3] = bias[c0 + 3];
    }
#pragma unroll
    for (int io = 0; io < 2; io++) {
#pragma unroll
        for (int i = 0; i < 4; i++) {
            const int r = rowBase + (ty << 2) + io * 64 + i;
            const int i8 = io * 4 + i;
#pragma unroll
            for (int jo = 0; jo < 2; jo++) {
                const int c0 = colBase + (tx << 2) + jo * 64;
                const float2 u0 = unpack2(acc2[i8][jo * 2 + 0]);
                const float2 u1 = unpack2(acc2[i8][jo * 2 + 1]);
                float4 v;
                v.x = u0.x + bfrag[jo][0];
                v.y = u0.y + bfrag[jo][1];
                v.z = u1.x + bfrag[jo][2];
                v.w = u1.y + bfrag[jo][3];
                if (MODE == 0) {
                    const int bb = r / NTOK, nn = r - bb * NTOK;
                    const int s = c0 >> 8, hh = (c0 >> 5) & 7, dd = c0 & 31;
                    float* dst = (s == 0) ? g_q : (s == 1) ? g_k : g_v;
                    if (s == 0) { v.x *= QSCALE; v.y *= QSCALE; v.z *= QSCALE; v.w *= QSCALE; }
                    *(float4*)&dst[(size_t)(((bb * NH + hh) * NTOK + nn) * HDIM + dd)] = v;
                } else {
                    *(float4*)&out[(size_t)r * CDIM + c0] = v;
                }
            }
        }
    }
}

// ---------------------------------------------------------------------------
// Fused attention: one CTA per (b, h). K^T and V resident in SMEM.
// 8 warps, each warp processes 4 q-rows at a time. QK^T uses packed FFMA2.
// Lane l owns score columns m in {4l..4l+3} and {128+4l..131+4l | l<17}.
// SMEM (floats): Kt[32][200] | Vs[196*32] | Bc[1184] | Pb[8][4][200] | Qs[8][4][32]
// ---------------------------------------------------------------------------
#define SM_KT 0
#define SM_VS 6400
#define SM_BC 12672
#define SM_PB 13856
#define SM_QS 20256
#define SM_FLOATS 21280
#define ATTN_SMEM_BYTES (SM_FLOATS * 4)

__global__ __launch_bounds__(256) void attn_kernel(
    const float* __restrict__ mask, const float* __restrict__ bias_table,
    const int* __restrict__ rel_index)
{
    extern __shared__ float sm[];
    float* Kt = sm + SM_KT;
    float* Vs = sm + SM_VS;
    float* Bc = sm + SM_BC;

    const int tid = threadIdx.x;
    const int lane = tid & 31, warp = tid >> 5;
    const int bh = blockIdx.x;
    const int b = bh >> 3, h = bh & 7;
    const size_t base = (size_t)bh * (NTOK * HDIM);

    // Fill K^T (padded stride 200), V, bias column for this head
    for (int idx = tid; idx < NTOK * HDIM; idx += 256) {
        const int m = idx >> 5, d = idx & 31;
        Kt[d * 200 + m] = g_k[base + idx];
        Vs[idx] = g_v[base + idx];
    }
    for (int i = tid; i < 1183; i += 256) Bc[i] = bias_table[i * NH + h];
    __syncthreads();

    const float4* Kt4 = (const float4*)Kt;              // stride 50 per d
    const int* riB = rel_index;
    const float* mkB = mask + (size_t)(b & 63) * (NTOK * NTOK);
    const bool g2 = (lane < 17);
    float* Qw = sm + SM_QS + warp * 128;                // [4][32]
    float* Pw = sm + SM_PB + warp * 800;                // [4][200]
    const float4* Qw4 = (const float4*)Qw;              // [4][8]

    for (int row0 = warp * 4; row0 < NTOK; row0 += 32) {
        // stage 4 q rows
#pragma unroll
        for (int r = 0; r < 4; r++)
            Qw[r * 32 + lane] = g_q[base + (size_t)(row0 + r) * HDIM + lane];
        __syncwarp();

        ull S2[4][4] = {};  // [r][pair] — pairs of score columns

        // QK^T with packed FFMA2; 4 rows share each K fragment
#pragma unroll
        for (int d4 = 0; d4 < 8; d4++) {
            float qa[4][4];
#pragma unroll
            for (int r = 0; r < 4; r++) {
                const float4 t = Qw4[r * 8 + d4];
                qa[r][0] = t.x; qa[r][1] = t.y; qa[r][2] = t.z; qa[r][3] = t.w;
            }
#pragma unroll
            for (int dd = 0; dd < 4; dd++) {
                const int d = d4 * 4 + dd;
                const float4 k0 = Kt4[d * 50 + lane];
                const ull kp0 = pack2(k0.x, k0.y);
                const ull kp1 = pack2(k0.z, k0.w);
                ull kp2 = 0, kp3 = 0;
                if (g2) {
                    const float4 k1 = Kt4[d * 50 + 32 + lane];
                    kp2 = pack2(k1.x, k1.y);
                    kp3 = pack2(k1.z, k1.w);
                }
#pragma unroll
                for (int r = 0; r < 4; r++) {
                    const ull q2 = pack2(qa[r][dd], qa[r][dd]);
                    FMA2(S2[r][0], q2, kp0, S2[r][0]);
                    FMA2(S2[r][1], q2, kp1, S2[r][1]);
                    if (g2) {
                        FMA2(S2[r][2], q2, kp2, S2[r][2]);
                        FMA2(S2[r][3], q2, kp3, S2[r][3]);
                    }
                }
            }
        }

        // unpack scores
        float S[4][8];
#pragma unroll
        for (int r = 0; r < 4; r++) {
#pragma unroll
            for (int p = 0; p < 4; p++) {
                const float2 u = unpack2(S2[r][p]);
                S[r][p * 2] = u.x; S[r][p * 2 + 1] = u.y;
            }
        }

        // bias + mask + softmax + stage P, per row
#pragma unroll
        for (int r = 0; r < 4; r++) {
            const int row = row0 + r;
            {
                const int4   i0 = ((const int4*)(riB + row * NTOK))[lane];
                const float4 m0 = ((const float4*)(mkB + (size_t)row * NTOK))[lane];
                S[r][0] += Bc[i0.x] + m0.x; S[r][1] += Bc[i0.y] + m0.y;
                S[r][2] += Bc[i0.z] + m0.z; S[r][3] += Bc[i0.w] + m0.w;
                if (g2) {
                    const int4   i1 = ((const int4*)(riB + row * NTOK))[32 + lane];
                    const float4 m1 = ((const float4*)(mkB + (size_t)row * NTOK))[32 + lane];
                    S[r][4] += Bc[i1.x] + m1.x; S[r][5] += Bc[i1.y] + m1.y;
                    S[r][6] += Bc[i1.z] + m1.z; S[r][7] += Bc[i1.w] + m1.w;
                }
            }
            float mx = fmaxf(fmaxf(S[r][0], S[r][1]), fmaxf(S[r][2], S[r][3]));
            if (g2) mx = fmaxf(mx, fmaxf(fmaxf(S[r][4], S[r][5]), fmaxf(S[r][6], S[r][7])));
#pragma unroll
            for (int off = 16; off; off >>= 1)
                mx = fmaxf(mx, __shfl_xor_sync(0xffffffffu, mx, off));

            float sum = 0.f;
#pragma unroll
            for (int j = 0; j < 4; j++) { S[r][j] = __expf(S[r][j] - mx); sum += S[r][j]; }
            if (g2) {
#pragma unroll
                for (int j = 4; j < 8; j++) { S[r][j] = __expf(S[r][j] - mx); sum += S[r][j]; }
            }
#pragma unroll
            for (int off = 16; off; off >>= 1)
                sum += __shfl_xor_sync(0xffffffffu, sum, off);
            const float inv = 1.0f / sum;
#pragma unroll
            for (int j = 0; j < 8; j++) S[r][j] *= inv;

            ((float4*)(Pw + r * 200))[lane] = make_float4(S[r][0], S[r][1], S[r][2], S[r][3]);
            if (g2)
                ((float4*)(Pw + r * 200))[32 + lane] = make_float4(S[r][4], S[r][5], S[r][6], S[r][7]);
        }
        __syncwarp();

        // PV: out[d=lane] per row; V fragment amortized over 4 rows
        float acc[4] = {0.f, 0.f, 0.f, 0.f};
#pragma unroll 7
        for (int g = 0; g < 49; g++) {
            const float* vr = Vs + g * 128 + lane;
            const float v0 = vr[0], v1 = vr[32], v2 = vr[64], v3 = vr[96];
#pragma unroll
            for (int r = 0; r < 4; r++) {
                const float4 p = ((const float4*)(Pw + r * 200))[g];
                acc[r] += p.x * v0 + p.y * v1 + p.z * v2 + p.w * v3;
            }
        }
#pragma unroll
        for (int r = 0; r < 4; r++)
            g_o[((size_t)b * NTOK + row0 + r) * CDIM + h * HDIM + lane] = acc[r];
        __syncwarp();
    }
}

// ---------------------------------------------------------------------------
extern "C" void kernel_launch(void* const* d_in, const int* in_sizes, int n_in,
                              void* d_out, int out_size)
{
    const float* x          = (const float*)d_in[0];
    const float* mask       = (const float*)d_in[1];
    const float* qkv_w      = (const float*)d_in[2];
    const float* qkv_b      = (const float*)d_in[3];
    const float* proj_w     = (const float*)d_in[4];
    const float* proj_b     = (const float*)d_in[5];
    const float* bias_table = (const float*)d_in[6];
    const int*   rel_index  = (const int*)d_in[7];
    float* out = (float*)d_out;

    cudaFuncSetAttribute(attn_kernel,
                         cudaFuncAttributeMaxDynamicSharedMemorySize,
                         ATTN_SMEM_BYTES);

    // 1) QKV projection -> g_q (scaled), g_k, g_v   (M=50176, N=768, K=256)
    gemm_kernel<0><<<dim3(6, MROWS / 128), 256>>>(x, qkv_w, qkv_b, nullptr);
    // 2) fused window attention -> g_o [B][N][C]
    attn_kernel<<<B__ * NH, 256, ATTN_SMEM_BYTES>>>(mask, bias_table, rel_index);
    // 3) output projection -> d_out                 (M=50176, N=256, K=256)
    gemm_kernel<1><<<dim3(2, MROWS / 128), 256>>>(nullptr, proj_w, proj_b, out);
}